// round 10
// baseline (speedup 1.0000x reference)
#include <cuda_runtime.h>
#include <cuda_fp16.h>
#include <math.h>

#define TWO_PI 6.283185307179586f
#define NPTS 131072

// ---- static device scratch (allocation-free) ----
__device__ __align__(16) __half2 g_A0[256 * 256 * 128];  // fp16 intermediates
__device__ __align__(16) __half2 g_A1[256 * 256 * 128];
__device__ __align__(16) __half2 g_A2[256 * 256 * 128];
__device__ __align__(16) __half2 g_Vx[256 * 256 * 128];  // channel-last volumes
__device__ __align__(16) __half2 g_Vy[256 * 256 * 128];
__device__ __align__(16) __half2 g_Vz[256 * 256 * 128];
// binning structures (3 planes x 32x32 bins of 8x8 texels)
__device__ unsigned g_hist[3072];
__device__ unsigned g_binstart[3073];
__device__ unsigned g_cursor[3072];
__device__ unsigned g_order[3 * NPTS];
// per-plane partial outputs
__device__ float g_part[3 * NPTS * 16];

#define SH_R 273   // smem row stride (float2 units)

// ---------------------------------------------------------------------------
// complex helpers
// ---------------------------------------------------------------------------
__device__ __forceinline__ float2 cmul(float2 a, float2 b) {
    return make_float2(fmaf(a.x, b.x, -a.y * b.y), fmaf(a.x, b.y, a.y * b.x));
}
__device__ __forceinline__ float2 cmul_imm(float2 a, float c, float s) {
    return make_float2(fmaf(a.x, c, a.y * (-s)), fmaf(a.y, c, a.x * s));
}
__device__ __forceinline__ float2 cadd(float2 a, float2 b) { return make_float2(a.x + b.x, a.y + b.y); }
__device__ __forceinline__ float2 csub(float2 a, float2 b) { return make_float2(a.x - b.x, a.y - b.y); }
__device__ __forceinline__ float2 muli(float2 a) { return make_float2(-a.y, a.x); }

__device__ __forceinline__ void dft4(float2 x0, float2 x1, float2 x2, float2 x3,
                                     float2& X0, float2& X1, float2& X2, float2& X3) {
    float2 t0 = cadd(x0, x2), t1 = csub(x0, x2);
    float2 t2 = cadd(x1, x3), t3 = csub(x1, x3);
    X0 = cadd(t0, t2);
    X2 = csub(t0, t2);
    float2 it3 = muli(t3);
    X1 = cadd(t1, it3);
    X3 = csub(t1, it3);
}

// inverse 16-point DFT, radix-4x4, natural-order in/out.
__device__ __forceinline__ void ifft16(const float2 x[16], float2 X[16]) {
    const float C  = 0.70710678118654752f;
    const float c1 = 0.92387953251128676f;
    const float s1 = 0.38268343236508977f;
    float2 y[16];
#pragma unroll
    for (int k1 = 0; k1 < 4; ++k1)
        dft4(x[k1], x[k1 + 4], x[k1 + 8], x[k1 + 12],
             y[4 * k1 + 0], y[4 * k1 + 1], y[4 * k1 + 2], y[4 * k1 + 3]);
    y[4 * 1 + 1] = cmul_imm(y[4 * 1 + 1],  c1,  s1);
    y[4 * 1 + 2] = cmul_imm(y[4 * 1 + 2],   C,   C);
    y[4 * 1 + 3] = cmul_imm(y[4 * 1 + 3],  s1,  c1);
    y[4 * 2 + 1] = cmul_imm(y[4 * 2 + 1],   C,   C);
    y[4 * 2 + 2] = muli(y[4 * 2 + 2]);
    y[4 * 2 + 3] = cmul_imm(y[4 * 2 + 3],  -C,   C);
    y[4 * 3 + 1] = cmul_imm(y[4 * 3 + 1],  s1,  c1);
    y[4 * 3 + 2] = cmul_imm(y[4 * 3 + 2],  -C,   C);
    y[4 * 3 + 3] = cmul_imm(y[4 * 3 + 3], -c1, -s1);
#pragma unroll
    for (int n2 = 0; n2 < 4; ++n2) {
        float2 z0, z1, z2, z3;
        dft4(y[4 * 0 + n2], y[4 * 1 + n2], y[4 * 2 + n2], y[4 * 3 + n2], z0, z1, z2, z3);
        X[n2] = z0; X[4 + n2] = z1; X[8 + n2] = z2; X[12 + n2] = z3;
    }
}

// 256-point inverse DFT core: stage-1 input x[k1] already in registers.
__device__ __forceinline__ void fft256_core(const float2 x[16], float2 (*sh)[SH_R],
                                            int line, int k0) {
    float2 X[16];
    ifft16(x, X);
    float sb, cb;
    __sincosf((float)k0 * (TWO_PI / 256.f), &sb, &cb);
    float2 base = make_float2(cb, sb);
    float2 tw = make_float2(1.f, 0.f);
#pragma unroll
    for (int n0 = 0; n0 < 16; ++n0) {
        sh[line][k0 * 17 + n0] = cmul(X[n0], tw);
        tw = cmul(tw, base);
    }
    __syncthreads();
    const int n0 = k0;
    float2 y[16];
#pragma unroll
    for (int kk = 0; kk < 16; ++kk) y[kk] = sh[line][kk * 17 + n0];
    __syncthreads();
    float2 Y[16];
    ifft16(y, Y);
#pragma unroll
    for (int n1 = 0; n1 < 16; ++n1) sh[line][n1 * 16 + n0] = Y[n1];
    __syncthreads();
}

// ----------------------------------------------------------------------------
// Pass 1 (all 3 volumes): inverse DFT along contiguous axis v.
// ----------------------------------------------------------------------------
__global__ __launch_bounds__(256) void k_fft_pass1_all(
        const float* __restrict__ x_re, const float* __restrict__ x_im,
        const float* __restrict__ y_re, const float* __restrict__ y_im,
        const float* __restrict__ z_re, const float* __restrict__ z_im,
        const float* __restrict__ alphap) {
    __shared__ float2 sh[16][SH_R];
    const int t = threadIdx.x;
    const int line = t >> 4, k0 = t & 15;

    const float ap = alphap[0];
    const float bxx = 10.f * ap;
    const float alpha = (bxx > 1.f) ? ap : 0.1f * log1pf(expf(fminf(bxx, 30.f)));

    const int bb = blockIdx.x;
    const int mode = bb >> 11;
    const int b = bb & 2047;
    const int u = b & 255;
    const int c0 = (b >> 8) * 16;

    float2 x[16];
    if (mode == 2) {
        const int f0 = c0 >> 3;
        const int base = f0 * 524288 + u * 2048;
#pragma unroll
        for (int j = 0; j < 16; ++j) {
            int e = t + 256 * j;
            int f_loc = e >> 11, r = e & 2047;
            int d = r & 7, v = r >> 3;
            sh[f_loc * 8 + d][v] = make_float2(z_re[base + f_loc * 524288 + r] * alpha,
                                               z_im[base + f_loc * 524288 + r] * alpha);
        }
        __syncthreads();
#pragma unroll
        for (int k1 = 0; k1 < 16; ++k1) x[k1] = sh[line][k1 * 16 + k0];
        __syncthreads();
    } else {
        const float* __restrict__ re = (mode == 0) ? x_re : y_re;
        const float* __restrict__ im = (mode == 0) ? x_im : y_im;
        int c = c0 + line;
        int base;
        if (mode == 0) base = c * 65536 + u * 256;
        else           base = (c >> 3) * 524288 + u * 2048 + (c & 7) * 256;
#pragma unroll
        for (int k1 = 0; k1 < 16; ++k1) {
            int idx = base + k1 * 16 + k0;
            x[k1] = make_float2(re[idx] * alpha, im[idx] * alpha);
        }
    }
    fft256_core(x, sh, line, k0);

    __half2* __restrict__ A = (mode == 0) ? g_A0 : (mode == 1) ? g_A1 : g_A2;
#pragma unroll
    for (int j = 0; j < 16; ++j) {
        int e = t + 256 * j;
        int cl = e & 15, v = e >> 4;
        float2 val = sh[cl][v];
        A[(u * 256 + v) * 128 + c0 + cl] = __floats2half2_rn(val.x, val.y);
    }
}

// ----------------------------------------------------------------------------
// Pass 2 (all 3 volumes): inverse DFT along u. Block = 16 channels at one v.
// ----------------------------------------------------------------------------
__global__ __launch_bounds__(256) void k_fft_pass2_all() {
    __shared__ float2 sh[16][SH_R];
    const int t = threadIdx.x;
    const int line = t >> 4, k0 = t & 15;

    const int bb = blockIdx.x;
    const int mode = bb >> 11;
    const int b = bb & 2047;
    const int v = b & 255;
    const int c0 = (b >> 8) * 16;

    const __half2* __restrict__ A = (mode == 0) ? g_A0 : (mode == 1) ? g_A1 : g_A2;
    __half2* __restrict__ V = (mode == 0) ? g_Vx : (mode == 1) ? g_Vy : g_Vz;

#pragma unroll
    for (int j = 0; j < 16; ++j) {
        int e = t + 256 * j;
        int cl = e & 15, u = e >> 4;
        sh[cl][u] = __half22float2(A[(u * 256 + v) * 128 + c0 + cl]);
    }
    __syncthreads();
    float2 x[16];
#pragma unroll
    for (int k1 = 0; k1 < 16; ++k1) x[k1] = sh[line][k1 * 16 + k0];
    __syncthreads();
    fft256_core(x, sh, line, k0);

#pragma unroll
    for (int j = 0; j < 16; ++j) {
        int e = t + 256 * j;
        int cl = e & 15, u = e >> 4;
        float2 val = sh[cl][u];
        V[(u * 256 + v) * 128 + c0 + cl] = __floats2half2_rn(val.x, val.y);
    }
}

// ----------------------------------------------------------------------------
// Binning: 32x32 bins of 8x8 texels per plane.
// ----------------------------------------------------------------------------
__device__ __forceinline__ int bin_of(float gu, float gv) {
    float iu = (gu + 1.f) * 127.5f;
    float iv = (gv + 1.f) * 127.5f;
    int u0 = min(max((int)floorf(iu), 0), 255);
    int v0 = min(max((int)floorf(iv), 0), 255);
    return (u0 >> 3) * 32 + (v0 >> 3);
}

__global__ __launch_bounds__(1024) void k_zero_hist() {
    int t = threadIdx.x;
    for (int i = t; i < 3072; i += 1024) g_hist[i] = 0;
}

__global__ __launch_bounds__(1024) void k_hist(const float* __restrict__ pts) {
    __shared__ unsigned h[3072];
    int t = threadIdx.x;
    for (int i = t; i < 3072; i += 1024) h[i] = 0;
    __syncthreads();
    int pid = blockIdx.x * 1024 + t;
    float xs = pts[pid * 3 + 0], ys = pts[pid * 3 + 1], zs = pts[pid * 3 + 2];
    atomicAdd(&h[bin_of(ys, zs)], 1u);
    atomicAdd(&h[1024 + bin_of(xs, zs)], 1u);
    atomicAdd(&h[2048 + bin_of(xs, ys)], 1u);
    __syncthreads();
    for (int i = t; i < 3072; i += 1024) if (h[i]) atomicAdd(&g_hist[i], h[i]);
}

__global__ __launch_bounds__(1024) void k_scan() {
    __shared__ unsigned s[1024];
    int t = threadIdx.x;
    unsigned a0 = g_hist[3 * t], a1 = g_hist[3 * t + 1], a2 = g_hist[3 * t + 2];
    unsigned tot = a0 + a1 + a2;
    s[t] = tot;
    __syncthreads();
    for (int off = 1; off < 1024; off <<= 1) {
        unsigned v = (t >= off) ? s[t - off] : 0u;
        __syncthreads();
        s[t] += v;
        __syncthreads();
    }
    unsigned excl = s[t] - tot;
    g_binstart[3 * t]     = excl;
    g_binstart[3 * t + 1] = excl + a0;
    g_binstart[3 * t + 2] = excl + a0 + a1;
    g_cursor[3 * t]     = excl;
    g_cursor[3 * t + 1] = excl + a0;
    g_cursor[3 * t + 2] = excl + a0 + a1;
    if (t == 1023) g_binstart[3072] = s[t];
}

__global__ __launch_bounds__(1024) void k_scatter(const float* __restrict__ pts) {
    int pid = blockIdx.x * 1024 + threadIdx.x;
    float xs = pts[pid * 3 + 0], ys = pts[pid * 3 + 1], zs = pts[pid * 3 + 2];
    unsigned s0 = atomicAdd(&g_cursor[bin_of(ys, zs)], 1u);
    g_order[s0] = (unsigned)pid;
    unsigned s1 = atomicAdd(&g_cursor[1024 + bin_of(xs, zs)], 1u);
    g_order[s1] = (unsigned)pid;
    unsigned s2 = atomicAdd(&g_cursor[2048 + bin_of(xs, ys)], 1u);
    g_order[s2] = (unsigned)pid;
}

// ----------------------------------------------------------------------------
// Binned sampler: block = (plane, bin). Loads 9x9-texel tile (41.5KB) into
// smem, serves all the bin's points from smem. Warp per point.
// Writes per-plane partials (no atomics).
// ----------------------------------------------------------------------------
__global__ __launch_bounds__(256) void k_sample_binned(const float* __restrict__ pts) {
    __shared__ uint4 tile[9 * 288];    // 9 rows x 9 texels x 32 uint4
    const int b = blockIdx.x;
    const int plane = b >> 10;
    const int bin = b & 1023;
    const int bu = bin >> 5, bv = bin & 31;
    const int t = threadIdx.x;

    const __half2* __restrict__ V = (plane == 0) ? g_Vx : (plane == 1) ? g_Vy : g_Vz;
    const int ncols_u4 = (bv == 31) ? 256 : 288;   // 8 or 9 texels x 32 uint4

    for (int i = t; i < 9 * 288; i += 256) {
        int r = i / 288, c = i % 288;
        if (c < ncols_u4) {
            int ur = min(bu * 8 + r, 255);
            const uint4* __restrict__ src = (const uint4*)(V + (ur * 256 + bv * 8) * 128);
            tile[r * 288 + c] = src[c];
        }
    }
    unsigned start = g_binstart[b], end = g_binstart[b + 1];
    __syncthreads();

    const int wid = t >> 5, lane = t & 31;
    const int d0 = (lane * 4) & 7;
    float* __restrict__ part = g_part + plane * (NPTS * 16);
    const float K = TWO_PI * 0.5f * (255.f / 256.f);

    for (unsigned i = start + wid; i < end; i += 8) {
        int pid = (int)g_order[i];
        float xs = pts[pid * 3 + 0], ys = pts[pid * 3 + 1], zs = pts[pid * 3 + 2];
        float gu, gv, tx;
        if (plane == 0)      { gu = ys; gv = zs; tx = xs; }
        else if (plane == 1) { gu = xs; gv = zs; tx = ys; }
        else                 { gu = xs; gv = ys; tx = zs; }

        float iu = (gu + 1.f) * 127.5f, iv = (gv + 1.f) * 127.5f;
        float u0f = floorf(iu), v0f = floorf(iv);
        float wu = iu - u0f, wv = iv - v0f;
        int u0 = min(max((int)u0f, 0), 255), v0 = min(max((int)v0f, 0), 255);
        int du = min(u0 + 1, 255) - u0, dv = min(v0 + 1, 255) - v0;
        int lu = u0 - bu * 8, lv = v0 - bv * 8;

        int base00 = (lu * 9 + lv) * 32 + lane;
        uint4 q00 = tile[base00];
        uint4 q01 = tile[base00 + dv * 32];
        uint4 q10 = tile[base00 + du * 288];
        uint4 q11 = tile[base00 + du * 288 + dv * 32];

        float w00 = (1.f - wu) * (1.f - wv), w01 = (1.f - wu) * wv;
        float w10 = wu * (1.f - wv),         w11 = wu * wv;

        float bang = (tx + 1.f) * K;
        float sn1, cn1;
        __sincosf(bang, &sn1, &cn1);
        float2 w1 = make_float2(cn1, sn1);
        float2 w2 = cmul(w1, w1);
        float2 w4 = cmul(w2, w2);
        float2 cur = (d0 == 0) ? make_float2(1.f, 0.f) : w4;

        const unsigned* a00 = (const unsigned*)&q00;
        const unsigned* a01 = (const unsigned*)&q01;
        const unsigned* a10 = (const unsigned*)&q10;
        const unsigned* a11 = (const unsigned*)&q11;

        float acc = 0.f;
#pragma unroll
        for (int j = 0; j < 4; ++j) {
            float2 a = __half22float2(*(const __half2*)&a00[j]);
            float2 bq = __half22float2(*(const __half2*)&a01[j]);
            float2 c = __half22float2(*(const __half2*)&a10[j]);
            float2 d = __half22float2(*(const __half2*)&a11[j]);
            float sr = w00 * a.x + w01 * bq.x + w10 * c.x + w11 * d.x;
            float si = w00 * a.y + w01 * bq.y + w10 * c.y + w11 * d.y;
            float sc = (d0 + j > 0) ? 2.f : 1.f;
            acc += sc * (sr * cur.x - si * cur.y);
            cur = cmul(cur, w1);
        }

        acc += __shfl_xor_sync(0xffffffffu, acc, 1);
        float vv = __shfl_sync(0xffffffffu, acc, (lane & 15) * 2);
        if (lane < 16) part[pid * 16 + lane] = vv;
    }
}

__global__ __launch_bounds__(1024) void k_combine(float* __restrict__ out) {
    int i = blockIdx.x * 1024 + threadIdx.x;   // 2,097,152 elements
    out[i] = g_part[i] + g_part[NPTS * 16 + i] + g_part[2 * NPTS * 16 + i];
}

extern "C" void kernel_launch(void* const* d_in, const int* in_sizes, int n_in,
                              void* d_out, int out_size) {
    const float* pts    = (const float*)d_in[0];
    const float* Fx_re  = (const float*)d_in[1];
    const float* Fx_im  = (const float*)d_in[2];
    const float* Fy_re  = (const float*)d_in[3];
    const float* Fy_im  = (const float*)d_in[4];
    const float* Fz_re  = (const float*)d_in[5];
    const float* Fz_im  = (const float*)d_in[6];
    const float* alphap = (const float*)d_in[7];
    float* out = (float*)d_out;

    k_zero_hist<<<1, 1024>>>();
    k_hist<<<128, 1024>>>(pts);
    k_scan<<<1, 1024>>>();
    k_scatter<<<128, 1024>>>(pts);
    k_fft_pass1_all<<<6144, 256>>>(Fx_re, Fx_im, Fy_re, Fy_im, Fz_re, Fz_im, alphap);
    k_fft_pass2_all<<<6144, 256>>>();
    k_sample_binned<<<3072, 256>>>(pts);
    k_combine<<<2048, 1024>>>(out);
}